// round 14
// baseline (speedup 1.0000x reference)
#include <cuda_runtime.h>
#include <cuda_fp16.h>
#include <stdint.h>
#include <math.h>

#define S_LEN   2048
#define DEMB    1024
#define MTOT    4096            // BATCH * S_LEN
#define NHEADS  16
#define DHEAD   64
#define D3      (3 * DEMB)

// ---------------- device scratch (allocation-free rule) ----------------
__device__ uint32_t g_qkvh[MTOT * D3 / 2];       // fp16 qkv, natural layout (half2 words)
__device__ uint32_t g_xf  [MTOT * DEMB / 2];     // x in fp16 A-frag order
__device__ uint32_t g_attf[MTOT * DEMB / 2];     // att in fp16 A-frag order (written by attn)
__device__ uint32_t g_wif [3 * DEMB * DEMB / 2]; // w_in fp16 B-frag order
__device__ uint32_t g_wof [DEMB * DEMB / 2];     // w_out fp16 B-frag order

// ---------------- helpers ----------------
__device__ __forceinline__ float ex2(float x) {
    float y; asm("ex2.approx.f32 %0, %1;" : "=f"(y) : "f"(x)); return y;
}
__device__ __forceinline__ void mma_f16(float* c, const uint32_t* a, const uint32_t* b) {
    asm volatile(
        "mma.sync.aligned.m16n8k16.row.col.f32.f16.f16.f32 "
        "{%0,%1,%2,%3}, {%4,%5,%6,%7}, {%8,%9}, {%0,%1,%2,%3};"
        : "+f"(c[0]), "+f"(c[1]), "+f"(c[2]), "+f"(c[3])
        : "r"(a[0]), "r"(a[1]), "r"(a[2]), "r"(a[3]), "r"(b[0]), "r"(b[1]));
}
__device__ __forceinline__ uint32_t packh2(float lo, float hi) {
    uint32_t r;
    asm("{ .reg .f16 l, h; cvt.rn.f16.f32 l, %1; cvt.rn.f16.f32 h, %2; mov.b32 %0, {l, h}; }"
        : "=r"(r) : "f"(lo), "f"(hi));
    return r;
}
__device__ __forceinline__ uint32_t smem_u32(const void* p) {
    uint32_t a;
    asm("{ .reg .u64 t; cvta.to.shared.u64 t, %1; cvt.u32.u64 %0, t; }" : "=r"(a) : "l"(p));
    return a;
}
__device__ __forceinline__ void cpa16(uint32_t dst, const void* src) {
    asm volatile("cp.async.cg.shared.global [%0], [%1], 16;" :: "r"(dst), "l"(src) : "memory");
}

// ---------------------------------------------------------------------------
// Repack kernels: natural fp32 -> fp16-packed fragment-ordered words.
// ---------------------------------------------------------------------------
__global__ void repack_A_h(const float* __restrict__ in, uint32_t* __restrict__ out, int K) {
    int gid  = blockIdx.x * 256 + threadIdx.x;      // one uint4 per thread
    int lane = gid & 31, tile = gid >> 5;
    int k16 = K >> 4;
    int tk = tile % k16, tm = tile / k16;
    int qr = lane >> 2, qc = lane & 3;
    const float* p = in + (size_t)(tm * 16 + qr) * K + tk * 16 + 2 * qc;
    uint4 u;
    u.x = packh2(p[0], p[1]);
    u.y = packh2(p[(size_t)8 * K], p[(size_t)8 * K + 1]);
    u.z = packh2(p[8], p[9]);
    u.w = packh2(p[(size_t)8 * K + 8], p[(size_t)8 * K + 9]);
    ((uint4*)out)[gid] = u;
}

__global__ void repack_B_h(const float* __restrict__ in, uint32_t* __restrict__ out, int K) {
    int gid  = blockIdx.x * 256 + threadIdx.x;      // one uint2 per thread
    int lane = gid & 31, tile = gid >> 5;
    int k16 = K >> 4;
    int tk = tile % k16, tn = tile / k16;
    int qr = lane >> 2, qc = lane & 3;
    const float* p = in + (size_t)(tn * 8 + qr) * K + tk * 16 + 2 * qc;
    uint2 u;
    u.x = packh2(p[0], p[1]);
    u.y = packh2(p[8], p[9]);
    ((uint2*)out)[gid] = u;
}

// ---------------------------------------------------------------------------
// Fragment-ordered fp16 GEMM: C = A @ W^T + bias.
// 128x128 CTA tile, BK=64, 2-stage cp.async double buffer.
// HALF_OUT is a compile-time template (regs stay <=128; 2 CTAs/SM pinned).
// ---------------------------------------------------------------------------
#define GSMEM 65536

__device__ __forceinline__ void gemm_copy_chunk(
    uint32_t sb, int stage, const char* Ab, const char* Bb,
    int tm0, int tn0, int k16, int c, int tid)
{
    uint32_t dA = sb + stage * 32768;
    uint32_t dB = dA + 16384;
    int tkc = c * 4;
    #pragma unroll
    for (int i = 0; i < 4; i++) {
        int seg = i * 256 + tid;
        int t = seg >> 5, off = (seg & 31) * 16;
        cpa16(dA + t * 512 + off,
              Ab + (size_t)((tm0 + (t >> 2)) * k16 + tkc + (t & 3)) * 512 + off);
    }
    #pragma unroll
    for (int i = 0; i < 4; i++) {
        int seg = i * 256 + tid;
        int t = seg >> 4, off = (seg & 15) * 16;
        cpa16(dB + t * 256 + off,
              Bb + (size_t)((tn0 + (t >> 2)) * k16 + tkc + (t & 3)) * 256 + off);
    }
    asm volatile("cp.async.commit_group;" ::: "memory");
}

template <int HALF_OUT>
__global__ __launch_bounds__(256, 2)
void gemm_frag(const uint32_t* __restrict__ Af, const uint32_t* __restrict__ Bf,
               const float* __restrict__ bias, void* __restrict__ Cout,
               int N, int K)
{
    extern __shared__ uint32_t smraw[];
    uint32_t sb = smem_u32(smraw);

    const int tid = threadIdx.x, wid = tid >> 5, lane = tid & 31;
    const int wm = wid >> 2, wn = wid & 3;
    const int qr = lane >> 2, qc = lane & 3;
    const int k16 = K >> 4;
    const int tm0 = blockIdx.y * 8, tn0 = blockIdx.x * 16;
    const int m0 = blockIdx.y * 128, n0 = blockIdx.x * 128;

    float acc[4][4][4];
    #pragma unroll
    for (int mi = 0; mi < 4; mi++)
        #pragma unroll
        for (int ni = 0; ni < 4; ni++)
            #pragma unroll
            for (int c = 0; c < 4; c++) acc[mi][ni][c] = 0.0f;

    const char* Ab = (const char*)Af;
    const char* Bb = (const char*)Bf;

    const int NC = K >> 6;
    gemm_copy_chunk(sb, 0, Ab, Bb, tm0, tn0, k16, 0, tid);

    for (int c = 0; c < NC; c++) {
        asm volatile("cp.async.wait_group 0;" ::: "memory");
        __syncthreads();
        if (c + 1 < NC)
            gemm_copy_chunk(sb, (c + 1) & 1, Ab, Bb, tm0, tn0, k16, c + 1, tid);

        uint32_t aB = sb + (c & 1) * 32768;
        uint32_t bB = aB + 16384;
        #pragma unroll
        for (int kt = 0; kt < 4; kt++) {
            uint4 af[4]; uint2 bf[4];
            #pragma unroll
            for (int mi = 0; mi < 4; mi++) {
                uint32_t addr = aB + (((wm * 4 + mi) * 4 + kt) * 512) + lane * 16;
                asm volatile("ld.shared.v4.u32 {%0,%1,%2,%3}, [%4];"
                    : "=r"(af[mi].x), "=r"(af[mi].y), "=r"(af[mi].z), "=r"(af[mi].w)
                    : "r"(addr));
            }
            #pragma unroll
            for (int ni = 0; ni < 4; ni++) {
                uint32_t addr = bB + (((wn * 4 + ni) * 4 + kt) * 256) + lane * 8;
                asm volatile("ld.shared.v2.u32 {%0,%1}, [%2];"
                    : "=r"(bf[ni].x), "=r"(bf[ni].y) : "r"(addr));
            }
            #pragma unroll
            for (int mi = 0; mi < 4; mi++)
                #pragma unroll
                for (int ni = 0; ni < 4; ni++)
                    mma_f16(acc[mi][ni], &af[mi].x, &bf[ni].x);
        }
    }

    #pragma unroll
    for (int mi = 0; mi < 4; mi++) {
        int r0 = m0 + wm * 64 + mi * 16 + qr;
        #pragma unroll
        for (int ni = 0; ni < 4; ni++) {
            int col = n0 + wn * 32 + ni * 8 + 2 * qc;
            float b0 = bias[col], b1 = bias[col + 1];
            float v00 = acc[mi][ni][0] + b0, v01 = acc[mi][ni][1] + b1;
            float v10 = acc[mi][ni][2] + b0, v11 = acc[mi][ni][3] + b1;
            if (HALF_OUT) {
                uint32_t* Ch = (uint32_t*)Cout;
                Ch[((size_t)r0 * N + col) >> 1]       = packh2(v00, v01);
                Ch[((size_t)(r0 + 8) * N + col) >> 1] = packh2(v10, v11);
            } else {
                float* C = (float*)Cout;
                *(float2*)(C + (size_t)r0 * N + col)       = make_float2(v00, v01);
                *(float2*)(C + (size_t)(r0 + 8) * N + col) = make_float2(v10, v11);
            }
        }
    }
}

// ---------------------------------------------------------------------------
// fp16 flash attention (m16n8k16), fp32 softmax (log2 domain).
// Reads fp16 qkv (half2 words); writes attf directly in A-fragment order.
// 128 queries x 1 head x 1 batch per block; 8 warps x 16 rows.
// ---------------------------------------------------------------------------
#define BSTR 66

__global__ __launch_bounds__(256)
void flash_attn(const uint32_t* __restrict__ qkvh, const int* __restrict__ maskp,
                uint4* __restrict__ attf)
{
    __shared__ uint32_t KF[32 * BSTR];
    __shared__ uint32_t VF[32 * BSTR];

    const int tid  = threadIdx.x;
    const int wid  = tid >> 5;
    const int lane = tid & 31;
    const int qr   = lane >> 2;
    const int qc   = lane & 3;
    const int qblk = gridDim.x - 1 - blockIdx.x;     // heavy blocks first
    const int q0 = qblk * 128;
    const int h  = blockIdx.y;
    const int b  = blockIdx.z;
    const int mask = *maskp;
    const uint32_t* base = qkvh + (size_t)b * S_LEN * (D3 / 2);

    const int row0 = q0 + wid * 16 + qr;
    const int row1 = row0 + 8;
    const int wmax = q0 + wid * 16 + 15;

    // Q fragments: direct half2 loads (qkv already fp16)
    uint32_t qf[4][4];
    {
        const uint32_t* q0p = base + (size_t)row0 * (D3 / 2) + h * (DHEAD / 2);
        const uint32_t* q1p = base + (size_t)row1 * (D3 / 2) + h * (DHEAD / 2);
        #pragma unroll
        for (int kk = 0; kk < 4; kk++) {
            qf[kk][0] = q0p[kk * 8 + qc];
            qf[kk][1] = q1p[kk * 8 + qc];
            qf[kk][2] = q0p[kk * 8 + qc + 4];
            qf[kk][3] = q1p[kk * 8 + qc + 4];
        }
    }

    float o[8][4];
    #pragma unroll
    for (int nd = 0; nd < 8; nd++)
        #pragma unroll
        for (int c = 0; c < 4; c++) o[nd][c] = 0.0f;
    float m0r = -1e30f, m1r = -1e30f, l0 = 0.0f, l1 = 0.0f;

    const float SCL = 0.125f * 1.4426950408889634f;
    const int ntiles = mask ? (q0 / 64 + 2) : (S_LEN / 64);

    const int lrb = tid >> 4;            // 0..15
    const int c4  = (tid & 15) * 4;      // 0..60

    // prefetch tile 0 (uint2 = 4 halves)
    uint2 kreg[4], vreg[4];
    #pragma unroll
    for (int i = 0; i < 4; i++) {
        int r = i * 16 + lrb;
        const uint32_t* kp = base + (size_t)r * (D3 / 2) + (DEMB + h * DHEAD + c4) / 2;
        kreg[i] = *(const uint2*)kp;
        vreg[i] = *(const uint2*)(kp + DEMB / 2);
    }

    __half* vf16 = (__half*)VF;

    for (int t = 0; t < ntiles; t++) {
        const int k0 = t * 64;
        __syncthreads();
        // scatter prefetched tile into fragment-order SMEM (pure moves for K)
        #pragma unroll
        for (int i = 0; i < 4; i++) {
            int r = i * 16 + lrb;
            {
                int g = (r >> 3) * 4 + (c4 >> 4);
                int cc = c4 & 15;
                int qc0 = (cc & 7) >> 1;
                int hi  = cc >> 3;
                int lbase = (r & 7) * 4 + qc0;
                KF[g * BSTR + lbase * 2 + hi]       = kreg[i].x;
                KF[g * BSTR + (lbase + 1) * 2 + hi] = kreg[i].y;
            }
            {
                int rr = r & 15;
                int vhi  = rr >> 3;
                int qcv  = (rr & 7) >> 1;
                int slot = rr & 1;
                const __half* vh = (const __half*)&vreg[i];
                int gk = (r >> 4) * 8;
                #pragma unroll
                for (int j = 0; j < 4; j++) {
                    int cV = c4 + j;
                    int gv = gk + (cV >> 3);
                    int lv = (cV & 7) * 4 + qcv;
                    vf16[(gv * BSTR + lv * 2 + vhi) * 2 + slot] = vh[j];
                }
            }
        }
        __syncthreads();
        // prefetch next tile (overlaps compute)
        if (t + 1 < ntiles) {
            int kn = (t + 1) * 64;
            #pragma unroll
            for (int i = 0; i < 4; i++) {
                int r = i * 16 + lrb;
                const uint32_t* kp = base + (size_t)(kn + r) * (D3 / 2) + (DEMB + h * DHEAD + c4) / 2;
                kreg[i] = *(const uint2*)kp;
                vreg[i] = *(const uint2*)(kp + DEMB / 2);
            }
        }
        if (mask && k0 > wmax) continue;

        // ----- S = Q @ K^T -----
        float s[8][4];
        #pragma unroll
        for (int ni = 0; ni < 8; ni++)
            #pragma unroll
            for (int c = 0; c < 4; c++) s[ni][c] = 0.0f;
        #pragma unroll
        for (int kk = 0; kk < 4; kk++) {
            #pragma unroll
            for (int ni = 0; ni < 8; ni++) {
                uint2 kf = *(const uint2*)&KF[(ni * 4 + kk) * BSTR + lane * 2];
                mma_f16(s[ni], qf[kk], &kf.x);
            }
        }

        const bool domask = mask && (k0 + 63 > row0);
        #pragma unroll
        for (int ni = 0; ni < 8; ni++) {
            #pragma unroll
            for (int c = 0; c < 4; c++) s[ni][c] *= SCL;
            if (domask) {
                int col = k0 + ni * 8 + 2 * qc;
                if (col     > row0) s[ni][0] = -1e30f;
                if (col + 1 > row0) s[ni][1] = -1e30f;
                if (col     > row1) s[ni][2] = -1e30f;
                if (col + 1 > row1) s[ni][3] = -1e30f;
            }
        }

        // ----- online softmax (log2 domain) -----
        float mx0 = -1e30f, mx1 = -1e30f;
        #pragma unroll
        for (int ni = 0; ni < 8; ni++) {
            mx0 = fmaxf(mx0, fmaxf(s[ni][0], s[ni][1]));
            mx1 = fmaxf(mx1, fmaxf(s[ni][2], s[ni][3]));
        }
        mx0 = fmaxf(mx0, __shfl_xor_sync(0xffffffffu, mx0, 1));
        mx0 = fmaxf(mx0, __shfl_xor_sync(0xffffffffu, mx0, 2));
        mx1 = fmaxf(mx1, __shfl_xor_sync(0xffffffffu, mx1, 1));
        mx1 = fmaxf(mx1, __shfl_xor_sync(0xffffffffu, mx1, 2));

        float mn0 = fmaxf(m0r, mx0), mn1 = fmaxf(m1r, mx1);
        float al0 = ex2(m0r - mn0), al1 = ex2(m1r - mn1);
        m0r = mn0; m1r = mn1;

        float rs0 = 0.0f, rs1 = 0.0f;
        #pragma unroll
        for (int ni = 0; ni < 8; ni++) {
            float p0 = ex2(s[ni][0] - mn0);
            float p1 = ex2(s[ni][1] - mn0);
            float p2 = ex2(s[ni][2] - mn1);
            float p3 = ex2(s[ni][3] - mn1);
            rs0 += p0 + p1; rs1 += p2 + p3;
            s[ni][0] = p0; s[ni][1] = p1; s[ni][2] = p2; s[ni][3] = p3;
        }
        rs0 += __shfl_xor_sync(0xffffffffu, rs0, 1);
        rs0 += __shfl_xor_sync(0xffffffffu, rs0, 2);
        rs1 += __shfl_xor_sync(0xffffffffu, rs1, 1);
        rs1 += __shfl_xor_sync(0xffffffffu, rs1, 2);
        l0 = l0 * al0 + rs0;
        l1 = l1 * al1 + rs1;
        #pragma unroll
        for (int nd = 0; nd < 8; nd++) {
            o[nd][0] *= al0; o[nd][1] *= al0;
            o[nd][2] *= al1; o[nd][3] *= al1;
        }

        // ----- O += P @ V : S C-layout IS the fp16 A-layout -----
        #pragma unroll
        for (int kk = 0; kk < 4; kk++) {
            uint32_t af[4];
            af[0] = packh2(s[2 * kk][0],     s[2 * kk][1]);
            af[1] = packh2(s[2 * kk][2],     s[2 * kk][3]);
            af[2] = packh2(s[2 * kk + 1][0], s[2 * kk + 1][1]);
            af[3] = packh2(s[2 * kk + 1][2], s[2 * kk + 1][3]);
            #pragma unroll
            for (int nd = 0; nd < 8; nd++) {
                uint2 vf = *(const uint2*)&VF[(kk * 8 + nd) * BSTR + lane * 2];
                mma_f16(o[nd], af, &vf.x);
            }
        }
    }

    // ----- normalize + store DIRECTLY in A-fragment order (fp16) -----
    const float inv0 = 1.0f / l0, inv1 = 1.0f / l1;
    const int tm = b * (S_LEN / 16) + q0 / 16 + wid;
    #pragma unroll
    for (int j = 0; j < 4; j++) {
        uint4 u;
        u.x = packh2(o[2 * j][0] * inv0,     o[2 * j][1] * inv0);
        u.y = packh2(o[2 * j][2] * inv1,     o[2 * j][3] * inv1);
        u.z = packh2(o[2 * j + 1][0] * inv0, o[2 * j + 1][1] * inv0);
        u.w = packh2(o[2 * j + 1][2] * inv1, o[2 * j + 1][3] * inv1);
        attf[(size_t)(tm * (DEMB / 16) + h * 4 + j) * 32 + lane] = u;
    }
}

// ---------------------------------------------------------------------------
extern "C" void kernel_launch(void* const* d_in, const int* in_sizes, int n_in,
                              void* d_out, int out_size)
{
    const float* x     = (const float*)d_in[0];
    const float* w_in  = (const float*)d_in[1];
    const float* b_in  = (const float*)d_in[2];
    const float* w_out = (const float*)d_in[3];
    const float* b_out = (const float*)d_in[4];
    const int*   maskp = (const int*)d_in[5];
    float* out = (float*)d_out;

    void *qkvh_p, *xf_p, *attf_p, *wif_p, *wof_p;
    cudaGetSymbolAddress(&qkvh_p, g_qkvh);
    cudaGetSymbolAddress(&xf_p, g_xf);
    cudaGetSymbolAddress(&attf_p, g_attf);
    cudaGetSymbolAddress(&wif_p, g_wif);
    cudaGetSymbolAddress(&wof_p, g_wof);
    uint32_t* qkvh = (uint32_t*)qkvh_p;
    uint32_t* xf   = (uint32_t*)xf_p;
    uint32_t* attf = (uint32_t*)attf_p;
    uint32_t* wif  = (uint32_t*)wif_p;
    uint32_t* wof  = (uint32_t*)wof_p;

    cudaFuncSetAttribute(gemm_frag<1>, cudaFuncAttributeMaxDynamicSharedMemorySize, GSMEM);
    cudaFuncSetAttribute(gemm_frag<0>, cudaFuncAttributeMaxDynamicSharedMemorySize, GSMEM);

    // 0) repack inputs into fp16 fragment order
    repack_A_h<<<(MTOT / 16) * (DEMB / 16) * 32 / 256, 256>>>(x, xf, DEMB);
    repack_B_h<<<(3 * DEMB / 8) * (DEMB / 16) * 32 / 256, 256>>>(w_in, wif, DEMB);
    repack_B_h<<<(DEMB / 8) * (DEMB / 16) * 32 / 256, 256>>>(w_out, wof, DEMB);

    // 1) QKV projection -> fp16 natural layout
    gemm_frag<1><<<dim3(3 * DEMB / 128, MTOT / 128), 256, GSMEM>>>(
        xf, wif, b_in, qkvh, 3 * DEMB, DEMB);

    // 2) causal flash attention -> attf in A-frag order
    flash_attn<<<dim3(S_LEN / 128, NHEADS, 2), 256>>>(qkvh, maskp, (uint4*)attf);

    // 3) output projection -> fp32 out
    gemm_frag<0><<<dim3(DEMB / 128, MTOT / 128), 256, GSMEM>>>(
        attf, wof, b_out, out, DEMB, DEMB);
}